// round 16
// baseline (speedup 1.0000x reference)
#include <cuda_runtime.h>
#include <cuda_bf16.h>
#include <math.h>

#define NB 32
#define NN 5000
#define NE 80000
#define CC 64
#define DIN 16
#define KP 30
#define FH 128
#define FTOT 208
#define FLATN (KP*FTOT + 1)   // 6241
#define NTOT ((size_t)NB*NN)  // 160000 rows
#define NNCC ((size_t)NN*CC)
#define BN_EPS 1e-5f

// ---------------- scratch (device globals; no allocation allowed) -------------
// Resolve with cudaGetSymbolAddress before passing to kernels (host shadows!).
// NOTE: zero-initialized at module load; k_topk_mlp restores the zero invariant
// at the end of every run, so no separate k_zero launch is needed.
__device__ float g_deg[NN];
__device__ float g_dinv[NN];
__device__ int   g_count[NN];
__device__ int   g_cursor[NN];
__device__ int   g_rowptr[NN + 1];
__device__ int2  g_csr[NE];            // packed (col, val-as-int)

__device__ float g_ax[NB * NN * DIN];  // layer-0 aggregated input (AX)
__device__ float g_xw[NB * NN * CC];   // GEMM output (spmm input)
__device__ float g_h1[NB * NN * CC];   // RAW (pre-BN) conv1 output
__device__ float g_h2[NB * NN * CC];   // RAW (pre-BN) conv2 output
__device__ float g_h3[NB * NN * CC];   // post-relu conv3 output

__device__ double g_bnsum[2 * CC];
__device__ double g_bnsumsq[2 * CC];
__device__ float  g_bnmu[2 * CC];
__device__ float  g_bnsc[2 * CC];
__device__ int    g_bnflag[2];

// ---------------- f32x2 helpers (sm_103a packed fp32) -------------------------
__device__ __forceinline__ unsigned long long pk2(float lo, float hi) {
    unsigned long long r;
    asm("mov.b64 %0, {%1, %2};" : "=l"(r) : "f"(lo), "f"(hi));
    return r;
}
__device__ __forceinline__ void upk2(unsigned long long v, float& lo, float& hi) {
    asm("mov.b64 {%0, %1}, %2;" : "=f"(lo), "=f"(hi) : "l"(v));
}
__device__ __forceinline__ unsigned long long ffma2(unsigned long long a,
                                                    unsigned long long b,
                                                    unsigned long long c) {
    unsigned long long d;
    asm("fma.rn.f32x2 %0, %1, %2, %3;" : "=l"(d) : "l"(a), "l"(b), "l"(c));
    return d;
}

// ---------------- BN finalize ticket (proven in R10/R11) ----------------------
__device__ __forceinline__ void bn_finalize_ticket(int slot, const float* __restrict__ gam,
                                                   int nblocks) {
    __shared__ int last;
    __syncthreads();
    if (threadIdx.x == 0) {
        __threadfence();
        int t = atomicAdd(&g_bnflag[slot], 1);
        last = (t == nblocks - 1) ? 1 : 0;
    }
    __syncthreads();
    if (last && threadIdx.x < CC) {
        __threadfence();
        const double invN = 1.0 / (double)(NB * NN);
        double mu = g_bnsum[slot * CC + threadIdx.x] * invN;
        double var = g_bnsumsq[slot * CC + threadIdx.x] * invN - mu * mu;
        g_bnmu[slot * CC + threadIdx.x] = (float)mu;
        g_bnsc[slot * CC + threadIdx.x] = rsqrtf((float)var + BN_EPS) * gam[threadIdx.x];
    }
}

// ---------------- graph setup -------------------------------------------------
__global__ void k_deg_accum(const float* __restrict__ attr, const int* __restrict__ erow) {
    int e = blockIdx.x * blockDim.x + threadIdx.x;
    if (e < NE) {
        int r = erow[e];
        atomicAdd(&g_deg[r], attr[e]);
        atomicAdd(&g_count[r], 1);
    }
}

// dinv + exclusive scan, single block of 1024
__global__ void k_dinv_scan() {
    __shared__ int s[1024];
    int tid = threadIdx.x;
    for (int i = tid; i < NN; i += 1024) {
        float d = g_deg[i] + 1.0f;  // self loop weight 1
        g_dinv[i] = (d > 0.f) ? rsqrtf(fmaxf(d, 1e-12f)) : 0.f;
    }
    const int CH = 5; // 1024*5 >= 5000
    int base = tid * CH;
    int vals[CH];
    int sum = 0;
    #pragma unroll
    for (int j = 0; j < CH; j++) {
        int idx = base + j;
        int v = (idx < NN) ? g_count[idx] : 0;
        vals[j] = sum;
        sum += v;
    }
    s[tid] = sum;
    __syncthreads();
    for (int off = 1; off < 1024; off <<= 1) {
        int v = (tid >= off) ? s[tid - off] : 0;
        __syncthreads();
        s[tid] += v;
        __syncthreads();
    }
    int excl = (tid == 0) ? 0 : s[tid - 1];
    #pragma unroll
    for (int j = 0; j < CH; j++) {
        int idx = base + j;
        if (idx < NN) g_rowptr[idx] = excl + vals[j];
    }
    if (tid == 1023) g_rowptr[NN] = s[1023];
}

__global__ void k_build_csr(const float* __restrict__ attr,
                            const int* __restrict__ erow,
                            const int* __restrict__ ecol) {
    int e = blockIdx.x * blockDim.x + threadIdx.x;
    if (e < NE) {
        int r = erow[e], c = ecol[e];
        float nv = g_dinv[r] * attr[e] * g_dinv[c];
        int pos = g_rowptr[r] + atomicAdd(&g_cursor[r], 1);
        int2 p; p.x = c; p.y = __float_as_int(nv);
        g_csr[pos] = p;
    }
}

// ---------------- SPMM 16-channel (layer-0), 2 batches per warp --------------
__global__ void k_spmm16(const float* __restrict__ x, float* __restrict__ ax) {
    int gw = (blockIdx.x * blockDim.x + threadIdx.x) >> 5;  // 0 .. NN*NB/2-1
    int lane = threadIdx.x & 31;
    if (gw >= NN * (NB / 2)) return;
    int r = gw % NN;
    int bp = gw / NN;                  // batch pair 0..15
    int b = bp * 2 + (lane >> 4);
    int ch = lane & 15;

    const float* base = x + (size_t)b * NN * DIN;
    float di = g_dinv[r];
    float acc = base[(size_t)r * DIN + ch] * di * di;

    int s = g_rowptr[r];
    int e = g_rowptr[r + 1];
    int i = s;
    for (; i + 4 <= e; i += 4) {
        int2 e0 = g_csr[i + 0], e1 = g_csr[i + 1], e2 = g_csr[i + 2], e3 = g_csr[i + 3];
        acc += __int_as_float(e0.y) * base[(size_t)e0.x * DIN + ch]
             + __int_as_float(e1.y) * base[(size_t)e1.x * DIN + ch]
             + __int_as_float(e2.y) * base[(size_t)e2.x * DIN + ch]
             + __int_as_float(e3.y) * base[(size_t)e3.x * DIN + ch];
    }
    for (; i < e; i++) {
        int2 e0 = g_csr[i];
        acc += __int_as_float(e0.y) * base[(size_t)e0.x * DIN + ch];
    }
    ax[((size_t)b * NN + r) * DIN + ch] = acc;
}

// ---------------- dense GEMM (f32x2 register-blocked): (M,K)@(K,64)->(M,64) --
// BNOUT: accumulate per-channel BN stats of outputs into slot_out (layer 0).
template <int K, bool BIAS, bool BNIN, bool BNOUT>
__global__ void k_gemm_rb(const float* __restrict__ in, const float* __restrict__ W,
                          const float* __restrict__ bias, const float* __restrict__ be,
                          int slot_in, int slot_out, const float* __restrict__ gam,
                          float* __restrict__ out) {
    __shared__ __align__(16) float Wp[K * CC];
    __shared__ __align__(16) float ssc[CC];
    __shared__ __align__(16) float sofs[CC];
    int tid = threadIdx.x;
    for (int i = tid; i < K * CC; i += 256) {
        int k = i / CC, ch = i - k * CC;
        Wp[(k >> 1) * (2 * CC) + ch * 2 + (k & 1)] = W[i];
    }
    if (BNIN && tid < CC) {
        float mu = g_bnmu[slot_in * CC + tid];
        float sc = g_bnsc[slot_in * CC + tid];
        ssc[tid] = sc;
        sofs[tid] = be[tid] - mu * sc;
    }
    __syncthreads();

    int c = (tid & 15) * 4;
    int rslot = tid >> 4;
    size_t m0 = (size_t)blockIdx.x * 128 + (size_t)rslot * 8;

    unsigned long long accP[8][4];
    #pragma unroll
    for (int r = 0; r < 8; r++)
        #pragma unroll
        for (int j = 0; j < 4; j++) accP[r][j] = 0ULL;

    #pragma unroll
    for (int k2 = 0; k2 < K / 2; k2 += 2) {           // 4 k-scalars per iter
        ulonglong2 bA = *(const ulonglong2*)(&Wp[(k2 + 0) * (2 * CC) + c * 2]);
        ulonglong2 bB = *(const ulonglong2*)(&Wp[(k2 + 0) * (2 * CC) + (c + 2) * 2]);
        ulonglong2 bC = *(const ulonglong2*)(&Wp[(k2 + 1) * (2 * CC) + c * 2]);
        ulonglong2 bD = *(const ulonglong2*)(&Wp[(k2 + 1) * (2 * CC) + (c + 2) * 2]);
        float4 sc4, of4;
        if (BNIN) {
            sc4 = *(const float4*)(&ssc[k2 * 2]);
            of4 = *(const float4*)(&sofs[k2 * 2]);
        }
        #pragma unroll
        for (int r = 0; r < 8; r++) {
            float4 av = *(const float4*)(in + (m0 + r) * K + k2 * 2);
            if (BNIN) {
                av.x = fmaxf(av.x * sc4.x + of4.x, 0.f);
                av.y = fmaxf(av.y * sc4.y + of4.y, 0.f);
                av.z = fmaxf(av.z * sc4.z + of4.z, 0.f);
                av.w = fmaxf(av.w * sc4.w + of4.w, 0.f);
            }
            unsigned long long p01 = pk2(av.x, av.y);
            unsigned long long p23 = pk2(av.z, av.w);
            accP[r][0] = ffma2(p01, bA.x, accP[r][0]);
            accP[r][1] = ffma2(p01, bA.y, accP[r][1]);
            accP[r][2] = ffma2(p01, bB.x, accP[r][2]);
            accP[r][3] = ffma2(p01, bB.y, accP[r][3]);
            accP[r][0] = ffma2(p23, bC.x, accP[r][0]);
            accP[r][1] = ffma2(p23, bC.y, accP[r][1]);
            accP[r][2] = ffma2(p23, bD.x, accP[r][2]);
            accP[r][3] = ffma2(p23, bD.y, accP[r][3]);
        }
    }

    float4 bv = make_float4(0.f, 0.f, 0.f, 0.f);
    if (BIAS) bv = *(const float4*)(bias + c);

    float4 s4 = make_float4(0.f, 0.f, 0.f, 0.f);
    float4 q4 = make_float4(0.f, 0.f, 0.f, 0.f);
    #pragma unroll
    for (int r = 0; r < 8; r++) {
        float lo, hi;
        float4 o;
        upk2(accP[r][0], lo, hi); o.x = lo + hi + bv.x;
        upk2(accP[r][1], lo, hi); o.y = lo + hi + bv.y;
        upk2(accP[r][2], lo, hi); o.z = lo + hi + bv.z;
        upk2(accP[r][3], lo, hi); o.w = lo + hi + bv.w;
        *(float4*)(out + (m0 + r) * CC + c) = o;
        if (BNOUT) {
            s4.x += o.x; s4.y += o.y; s4.z += o.z; s4.w += o.w;
            q4.x += o.x * o.x; q4.y += o.y * o.y; q4.z += o.z * o.z; q4.w += o.w * o.w;
        }
    }

    if (BNOUT) {
        __shared__ __align__(16) float rsum[16 * 64];
        __shared__ __align__(16) float rsq[16 * 64];
        *(float4*)(&rsum[rslot * 64 + c]) = s4;
        *(float4*)(&rsq[rslot * 64 + c])  = q4;
        __syncthreads();
        if (tid < CC) {
            float ts = 0.f, tq = 0.f;
            #pragma unroll
            for (int j = 0; j < 16; j++) { ts += rsum[j * 64 + tid]; tq += rsq[j * 64 + tid]; }
            atomicAdd(&g_bnsum[slot_out * CC + tid], (double)ts);
            atomicAdd(&g_bnsumsq[slot_out * CC + tid], (double)tq);
        }
        bn_finalize_ticket(slot_out, gam, gridDim.x);
    }
}

// ---------------- SPMM 64-ch: warp per (b,row), 2 edges in flight -------------
// BNOUT: accumulate BN stats of outputs into slot (layer-1 SPMM).
template <bool RELU, bool BNOUT>
__global__ void k_spmm(const float* __restrict__ xw, const float* __restrict__ bias,
                       float* __restrict__ out, int slot, const float* __restrict__ gam) {
    int gw = (blockIdx.x * blockDim.x + threadIdx.x) >> 5;
    int lane = threadIdx.x & 31;
    int warp = threadIdx.x >> 5;   // 0..7
    int b = gw / NN;
    int r = gw - b * NN;
    int half = lane >> 4;
    int c0 = (lane & 15) * 4;

    const float* base = xw + (size_t)b * NNCC;
    float4 acc = make_float4(0.f, 0.f, 0.f, 0.f);
    if (half == 0) {
        float di = g_dinv[r];
        float sl = di * di;
        float4 sv = *(const float4*)(base + (size_t)r * CC + c0);
        acc.x = sv.x * sl; acc.y = sv.y * sl; acc.z = sv.z * sl; acc.w = sv.w * sl;
    }

    int s = g_rowptr[r];
    int e = g_rowptr[r + 1];
    int i = s;
    for (; i + 4 <= e; i += 4) {               // 2 edge-pairs per iter
        int2 eA = g_csr[i + half];
        int2 eB = g_csr[i + 2 + half];
        float wA = __int_as_float(eA.y);
        float wB = __int_as_float(eB.y);
        float4 vA = *(const float4*)(base + (size_t)eA.x * CC + c0);
        float4 vB = *(const float4*)(base + (size_t)eB.x * CC + c0);
        acc.x += wA * vA.x + wB * vB.x;
        acc.y += wA * vA.y + wB * vB.y;
        acc.z += wA * vA.z + wB * vB.z;
        acc.w += wA * vA.w + wB * vB.w;
    }
    if (i + 2 <= e) {                          // one edge-pair
        int2 eA = g_csr[i + half];
        float wA = __int_as_float(eA.y);
        float4 vA = *(const float4*)(base + (size_t)eA.x * CC + c0);
        acc.x += wA * vA.x; acc.y += wA * vA.y;
        acc.z += wA * vA.z; acc.w += wA * vA.w;
        i += 2;
    }
    if (i < e && half == 0) {                  // odd remainder edge
        int2 eA = g_csr[i];
        float wA = __int_as_float(eA.y);
        float4 vA = *(const float4*)(base + (size_t)eA.x * CC + c0);
        acc.x += wA * vA.x; acc.y += wA * vA.y;
        acc.z += wA * vA.z; acc.w += wA * vA.w;
    }

    // combine even/odd halves (both end with the full sum)
    acc.x += __shfl_xor_sync(0xffffffffu, acc.x, 16);
    acc.y += __shfl_xor_sync(0xffffffffu, acc.y, 16);
    acc.z += __shfl_xor_sync(0xffffffffu, acc.z, 16);
    acc.w += __shfl_xor_sync(0xffffffffu, acc.w, 16);

    if (half == 0) {
        float4 bq = *(const float4*)(bias + c0);
        acc.x += bq.x; acc.y += bq.y; acc.z += bq.z; acc.w += bq.w;
        if (RELU) {
            acc.x = fmaxf(acc.x, 0.f); acc.y = fmaxf(acc.y, 0.f);
            acc.z = fmaxf(acc.z, 0.f); acc.w = fmaxf(acc.w, 0.f);
        }
        *(float4*)(out + ((size_t)b * NN + r) * CC + c0) = acc;
    }

    if (BNOUT) {
        __shared__ __align__(16) float rsum[8 * 64];
        __shared__ __align__(16) float rsq[8 * 64];
        if (half == 0) {
            float4 q;
            q.x = acc.x * acc.x; q.y = acc.y * acc.y;
            q.z = acc.z * acc.z; q.w = acc.w * acc.w;
            *(float4*)(&rsum[warp * 64 + c0]) = acc;
            *(float4*)(&rsq[warp * 64 + c0])  = q;
        }
        __syncthreads();
        if (threadIdx.x < CC) {
            float ts = 0.f, tq = 0.f;
            #pragma unroll
            for (int j = 0; j < 8; j++) { ts += rsum[j * 64 + threadIdx.x]; tq += rsq[j * 64 + threadIdx.x]; }
            atomicAdd(&g_bnsum[slot * CC + threadIdx.x], (double)ts);
            atomicAdd(&g_bnsumsq[slot * CC + threadIdx.x], (double)tq);
        }
        bn_finalize_ticket(slot, gam, gridDim.x);
    }
}

// ---------------- top-k sort pool + MLP1 + MLP2 (merged, 1024 thr) -----------
__device__ __forceinline__ void argmax_red32(float& v, int& i) {
    #pragma unroll
    for (int off = 16; off; off >>= 1) {
        float v2 = __shfl_down_sync(0xffffffffu, v, off);
        int   i2 = __shfl_down_sync(0xffffffffu, i, off);
        if (v2 > v || (v2 == v && i2 < i)) { v = v2; i = i2; }
    }
}

#define NSLC 32
#define SLW32 ((FLATN + NSLC - 1) / NSLC)   // 196
__global__ void k_topk_mlp(const float* __restrict__ x, const float* __restrict__ age,
                           const float* __restrict__ mW0, const float* __restrict__ mb0,
                           const float* __restrict__ mW1, const float* __restrict__ mb1,
                           const float* __restrict__ be0, const float* __restrict__ be1,
                           float* __restrict__ out) {
    __shared__ __align__(16) float flat[FLATN + 3];    // padded; phase1: key[5000]
    __shared__ __align__(16) float part[NSLC * FH];    // slice partials
    __shared__ __align__(16) float hm_s[FH];
    __shared__ float swv[32];
    __shared__ int   swi[32];
    __shared__ int   sel[KP];
    int b = blockIdx.x;
    int t = threadIdx.x;           // 0..1023
    int lane = t & 31, wid = t >> 5;

    // ---- phase 0 (block 0): restore zero invariant for next graph replay ----
    if (b == 0) {
        for (int i = t; i < NN; i += 1024) { g_deg[i] = 0.f; g_count[i] = 0; g_cursor[i] = 0; }
        if (t < 2 * CC) { g_bnsum[t] = 0.0; g_bnsumsq[t] = 0.0; }
        if (t < 2) g_bnflag[t] = 0;
    }

    // ---- phase 1: top-30 of h3[:, :, 63] (stable: val desc, idx asc) ----
    float* key = flat;
    for (int n = t; n < NN; n += 1024)
        key[n] = g_h3[((size_t)b * NN + n) * CC + 63];
    __syncthreads();
    for (int it = 0; it < KP; it++) {
        float best = -INFINITY;
        int bidx = NN;
        for (int n = t; n < NN; n += 1024) {
            float v = key[n];
            if (v > best || (v == best && n < bidx)) { best = v; bidx = n; }
        }
        argmax_red32(best, bidx);
        if (lane == 0) { swv[wid] = best; swi[wid] = bidx; }
        __syncthreads();
        if (wid == 0) {
            float v = swv[lane];
            int i = swi[lane];
            argmax_red32(v, i);
            if (lane == 0) { sel[it] = i; key[i] = -INFINITY; }
        }
        __syncthreads();
    }

    // ---- phase 2: gather flat features (BN+relu applied to h1/h2) ----
    for (int i = t; i < KP * FTOT; i += 1024) {
        int k = i / FTOT;
        int f = i - k * FTOT;
        int n = sel[k];
        size_t bn = (size_t)b * NN + n;
        float v;
        if (f < DIN) {
            v = x[bn * DIN + f];
        } else if (f < DIN + CC) {
            int c = f - DIN;
            v = fmaxf((g_h1[bn * CC + c] - g_bnmu[c]) * g_bnsc[c] + be0[c], 0.f);
        } else if (f < DIN + 2 * CC) {
            int c = f - DIN - CC;
            v = fmaxf((g_h2[bn * CC + c] - g_bnmu[CC + c]) * g_bnsc[CC + c] + be1[c], 0.f);
        } else {
            v = g_h3[bn * CC + (f - DIN - 2 * CC)];
        }
        flat[i] = v;
    }
    if (t == 0) flat[KP * FTOT] = age[b];
    __syncthreads();

    // ---- MLP layer 1: thread = (neuron-quad = lane, slice = warp) ----
    {
        int n0 = lane * 4;          // neuron quad base (lane 0..31 covers 128)
        int slice = wid;            // 0..31
        int i0 = slice * SLW32;
        int i1 = min(i0 + SLW32, FLATN);
        float4 a = make_float4(0.f, 0.f, 0.f, 0.f);
        for (int i = i0; i < i1; i++) {
            float fv = flat[i];
            float4 w = *(const float4*)(mW0 + (size_t)i * FH + n0);
            a.x += fv * w.x; a.y += fv * w.y; a.z += fv * w.z; a.w += fv * w.w;
        }
        *(float4*)(&part[slice * FH + n0]) = a;
    }
    __syncthreads();

    if (t < FH) {
        float accn = mb0[t];
        #pragma unroll 8
        for (int sl2 = 0; sl2 < NSLC; sl2++) accn += part[sl2 * FH + t];
        hm_s[t] = fmaxf(accn, 0.f);
    }
    __syncthreads();

    // ---- MLP layer 2 + log_softmax (warp 0) ----
    if (t < 32) {
        float p0 = 0.f, p1 = 0.f;
        #pragma unroll
        for (int jj = t; jj < FH; jj += 32) {
            float v = hm_s[jj];
            float2 w = *(const float2*)(mW1 + jj * 2);
            p0 += v * w.x; p1 += v * w.y;
        }
        #pragma unroll
        for (int off = 16; off; off >>= 1) {
            p0 += __shfl_down_sync(0xffffffffu, p0, off);
            p1 += __shfl_down_sync(0xffffffffu, p1, off);
        }
        if (t == 0) {
            float a0 = p0 + mb1[0], a1 = p1 + mb1[1];
            float m = fmaxf(a0, a1);
            float lse = m + logf(expf(a0 - m) + expf(a1 - m));
            out[b * 2 + 0] = a0 - lse;
            out[b * 2 + 1] = a1 - lse;
        }
    }
}

// ---------------- driver ------------------------------------------------------
extern "C" void kernel_launch(void* const* d_in, const int* in_sizes, int n_in,
                              void* d_out, int out_size) {
    const float* x    = (const float*)d_in[0];
    const float* age  = (const float*)d_in[1];
    const float* attr = (const float*)d_in[2];
    const float* W0   = (const float*)d_in[3];
    const float* b0   = (const float*)d_in[4];
    const float* W1   = (const float*)d_in[5];
    const float* b1   = (const float*)d_in[6];
    const float* W2   = (const float*)d_in[7];
    const float* b2   = (const float*)d_in[8];
    const float* g0   = (const float*)d_in[9];
    const float* be0  = (const float*)d_in[10];
    const float* g1   = (const float*)d_in[11];
    const float* be1  = (const float*)d_in[12];
    const float* mW0  = (const float*)d_in[13];
    const float* mb0  = (const float*)d_in[14];
    const float* mW1  = (const float*)d_in[15];
    const float* mb1  = (const float*)d_in[16];
    const int*   erow = (const int*)d_in[17];
    const int*   ecol = (const int*)d_in[18];
    float* out = (float*)d_out;

    // Resolve REAL device addresses of scratch symbols (host-side query; capture-safe).
    float *p_ax = nullptr, *p_xw = nullptr, *p_h1 = nullptr, *p_h2 = nullptr, *p_h3 = nullptr;
    cudaGetSymbolAddress((void**)&p_ax, g_ax);
    cudaGetSymbolAddress((void**)&p_xw, g_xw);
    cudaGetSymbolAddress((void**)&p_h1, g_h1);
    cudaGetSymbolAddress((void**)&p_h2, g_h2);
    cudaGetSymbolAddress((void**)&p_h3, g_h3);

    // graph normalization + CSR build (3 launches; zero invariant maintained
    // by k_topk_mlp at the end of the previous run / module load)
    k_deg_accum<<<(NE + 255) / 256, 256>>>(attr, erow);
    k_dinv_scan<<<1, 1024>>>();
    k_build_csr<<<(NE + 255) / 256, 256>>>(attr, erow, ecol);

    const int spmm16_blocks = (NN * (NB / 2) * 32 + 255) / 256; // 2 batches per warp
    const int spmm_blocks = (NB * NN * 32 + 255) / 256;         // warp per (b,row), exact
    const int gemm_blocks = (int)(NTOT / 128);                  // 1250, exact

    // layer 0: aggregate (A X) then dense (AX)@W0 + b0; h1 RAW; BN0 stats fused
    k_spmm16<<<spmm16_blocks, 256>>>(x, p_ax);
    k_gemm_rb<DIN, true, false, true><<<gemm_blocks, 256>>>(p_ax, W0, b0, nullptr, 0, 0, g0, p_h1);

    // layer 1: xw = bnrelu0(h1) @ W1; h2 = A xw + b1 (BN1 stats fused)
    k_gemm_rb<CC, false, true, false><<<gemm_blocks, 256>>>(p_h1, W1, nullptr, be0, 0, 0, nullptr, p_xw);
    k_spmm<false, true><<<spmm_blocks, 256>>>(p_xw, b1, p_h2, 1, g1);

    // layer 2: xw = bnrelu1(h2) @ W2; h3 = relu(A xw + b2)
    k_gemm_rb<CC, false, true, false><<<gemm_blocks, 256>>>(p_h2, W2, nullptr, be1, 1, 0, nullptr, p_xw);
    k_spmm<true, false><<<spmm_blocks, 256>>>(p_xw, b2, p_h3, 0, nullptr);

    // sort pooling + MLP head (fully fused) + scratch re-zero for next replay
    k_topk_mlp<<<NB, 1024>>>(x, age, mW0, mb0, mW1, mb1, be0, be1, out);
}

// round 17
// speedup vs baseline: 1.2482x; 1.2482x over previous
#include <cuda_runtime.h>
#include <cuda_bf16.h>
#include <math.h>

#define NB 32
#define NN 5000
#define NE 80000
#define CC 64
#define DIN 16
#define KP 30
#define FH 128
#define FTOT 208
#define FLATN (KP*FTOT + 1)   // 6241
#define NTOT ((size_t)NB*NN)  // 160000 rows
#define NNCC ((size_t)NN*CC)
#define BN_EPS 1e-5f

// ---------------- scratch (device globals; no allocation allowed) -------------
// Resolve with cudaGetSymbolAddress before passing to kernels (host shadows!).
// Zero-initialized at module load; k_topk_mlp block 0 restores the zero
// invariant at the end of every run (so no k_zero launch is needed).
__device__ float g_deg[NN];
__device__ float g_dinv[NN];
__device__ int   g_count[NN];
__device__ int   g_cursor[NN];
__device__ int   g_rowptr[NN + 1];
__device__ int2  g_csr[NE];            // packed (col, val-as-int)

__device__ float g_ax[NB * NN * DIN];  // layer-0 aggregated input (AX)
__device__ float g_xw[NB * NN * CC];   // GEMM output (spmm input)
__device__ float g_h1[NB * NN * CC];   // RAW (pre-BN) conv1 output
__device__ float g_h2[NB * NN * CC];   // RAW (pre-BN) conv2 output
__device__ float g_h3[NB * NN * CC];   // post-relu conv3 output

__device__ double g_bnsum[2 * CC];
__device__ double g_bnsumsq[2 * CC];
__device__ float  g_bnmu[2 * CC];
__device__ float  g_bnsc[2 * CC];
__device__ int    g_bnflag[2];

// ---------------- f32x2 helpers (sm_103a packed fp32) -------------------------
__device__ __forceinline__ unsigned long long pk2(float lo, float hi) {
    unsigned long long r;
    asm("mov.b64 %0, {%1, %2};" : "=l"(r) : "f"(lo), "f"(hi));
    return r;
}
__device__ __forceinline__ void upk2(unsigned long long v, float& lo, float& hi) {
    asm("mov.b64 {%0, %1}, %2;" : "=f"(lo), "=f"(hi) : "l"(v));
}
__device__ __forceinline__ unsigned long long ffma2(unsigned long long a,
                                                    unsigned long long b,
                                                    unsigned long long c) {
    unsigned long long d;
    asm("fma.rn.f32x2 %0, %1, %2, %3;" : "=l"(d) : "l"(a), "l"(b), "l"(c));
    return d;
}

// ---------------- graph setup -------------------------------------------------
__global__ void k_deg_accum(const float* __restrict__ attr, const int* __restrict__ erow) {
    int e = blockIdx.x * blockDim.x + threadIdx.x;
    if (e < NE) {
        int r = erow[e];
        atomicAdd(&g_deg[r], attr[e]);
        atomicAdd(&g_count[r], 1);
    }
}

// dinv + exclusive scan, single block of 1024
__global__ void k_dinv_scan() {
    __shared__ int s[1024];
    int tid = threadIdx.x;
    for (int i = tid; i < NN; i += 1024) {
        float d = g_deg[i] + 1.0f;  // self loop weight 1
        g_dinv[i] = (d > 0.f) ? rsqrtf(fmaxf(d, 1e-12f)) : 0.f;
    }
    const int CH = 5; // 1024*5 >= 5000
    int base = tid * CH;
    int vals[CH];
    int sum = 0;
    #pragma unroll
    for (int j = 0; j < CH; j++) {
        int idx = base + j;
        int v = (idx < NN) ? g_count[idx] : 0;
        vals[j] = sum;
        sum += v;
    }
    s[tid] = sum;
    __syncthreads();
    for (int off = 1; off < 1024; off <<= 1) {
        int v = (tid >= off) ? s[tid - off] : 0;
        __syncthreads();
        s[tid] += v;
        __syncthreads();
    }
    int excl = (tid == 0) ? 0 : s[tid - 1];
    #pragma unroll
    for (int j = 0; j < CH; j++) {
        int idx = base + j;
        if (idx < NN) g_rowptr[idx] = excl + vals[j];
    }
    if (tid == 1023) g_rowptr[NN] = s[1023];
}

__global__ void k_build_csr(const float* __restrict__ attr,
                            const int* __restrict__ erow,
                            const int* __restrict__ ecol) {
    int e = blockIdx.x * blockDim.x + threadIdx.x;
    if (e < NE) {
        int r = erow[e], c = ecol[e];
        float nv = g_dinv[r] * attr[e] * g_dinv[c];
        int pos = g_rowptr[r] + atomicAdd(&g_cursor[r], 1);
        int2 p; p.x = c; p.y = __float_as_int(nv);
        g_csr[pos] = p;
    }
}

// ---------------- SPMM 16-channel (layer-0), 2 batches per warp --------------
__global__ void k_spmm16(const float* __restrict__ x, float* __restrict__ ax) {
    int gw = (blockIdx.x * blockDim.x + threadIdx.x) >> 5;  // 0 .. NN*NB/2-1
    int lane = threadIdx.x & 31;
    if (gw >= NN * (NB / 2)) return;
    int r = gw % NN;
    int bp = gw / NN;                  // batch pair 0..15
    int b = bp * 2 + (lane >> 4);
    int ch = lane & 15;

    const float* base = x + (size_t)b * NN * DIN;
    float di = g_dinv[r];
    float acc = base[(size_t)r * DIN + ch] * di * di;

    int s = g_rowptr[r];
    int e = g_rowptr[r + 1];
    int i = s;
    for (; i + 4 <= e; i += 4) {
        int2 e0 = g_csr[i + 0], e1 = g_csr[i + 1], e2 = g_csr[i + 2], e3 = g_csr[i + 3];
        acc += __int_as_float(e0.y) * base[(size_t)e0.x * DIN + ch]
             + __int_as_float(e1.y) * base[(size_t)e1.x * DIN + ch]
             + __int_as_float(e2.y) * base[(size_t)e2.x * DIN + ch]
             + __int_as_float(e3.y) * base[(size_t)e3.x * DIN + ch];
    }
    for (; i < e; i++) {
        int2 e0 = g_csr[i];
        acc += __int_as_float(e0.y) * base[(size_t)e0.x * DIN + ch];
    }
    ax[((size_t)b * NN + r) * DIN + ch] = acc;
}

// ---------------- dense GEMM (f32x2 register-blocked): (M,K)@(K,64)->(M,64) --
template <int K, bool BIAS, bool BNIN>
__global__ void k_gemm_rb(const float* __restrict__ in, const float* __restrict__ W,
                          const float* __restrict__ bias, const float* __restrict__ be,
                          int slot, float* __restrict__ out) {
    __shared__ __align__(16) float Wp[K * CC];
    __shared__ __align__(16) float ssc[CC];
    __shared__ __align__(16) float sofs[CC];
    int tid = threadIdx.x;
    for (int i = tid; i < K * CC; i += 256) {
        int k = i / CC, ch = i - k * CC;
        Wp[(k >> 1) * (2 * CC) + ch * 2 + (k & 1)] = W[i];
    }
    if (BNIN && tid < CC) {
        float mu = g_bnmu[slot * CC + tid];
        float sc = g_bnsc[slot * CC + tid];
        ssc[tid] = sc;
        sofs[tid] = be[tid] - mu * sc;
    }
    __syncthreads();

    int c = (tid & 15) * 4;
    int rslot = tid >> 4;
    size_t m0 = (size_t)blockIdx.x * 128 + (size_t)rslot * 8;

    unsigned long long accP[8][4];
    #pragma unroll
    for (int r = 0; r < 8; r++)
        #pragma unroll
        for (int j = 0; j < 4; j++) accP[r][j] = 0ULL;

    #pragma unroll
    for (int k2 = 0; k2 < K / 2; k2 += 2) {           // 4 k-scalars per iter
        ulonglong2 bA = *(const ulonglong2*)(&Wp[(k2 + 0) * (2 * CC) + c * 2]);
        ulonglong2 bB = *(const ulonglong2*)(&Wp[(k2 + 0) * (2 * CC) + (c + 2) * 2]);
        ulonglong2 bC = *(const ulonglong2*)(&Wp[(k2 + 1) * (2 * CC) + c * 2]);
        ulonglong2 bD = *(const ulonglong2*)(&Wp[(k2 + 1) * (2 * CC) + (c + 2) * 2]);
        float4 sc4, of4;
        if (BNIN) {
            sc4 = *(const float4*)(&ssc[k2 * 2]);
            of4 = *(const float4*)(&sofs[k2 * 2]);
        }
        #pragma unroll
        for (int r = 0; r < 8; r++) {
            float4 av = *(const float4*)(in + (m0 + r) * K + k2 * 2);
            if (BNIN) {
                av.x = fmaxf(av.x * sc4.x + of4.x, 0.f);
                av.y = fmaxf(av.y * sc4.y + of4.y, 0.f);
                av.z = fmaxf(av.z * sc4.z + of4.z, 0.f);
                av.w = fmaxf(av.w * sc4.w + of4.w, 0.f);
            }
            unsigned long long p01 = pk2(av.x, av.y);
            unsigned long long p23 = pk2(av.z, av.w);
            accP[r][0] = ffma2(p01, bA.x, accP[r][0]);
            accP[r][1] = ffma2(p01, bA.y, accP[r][1]);
            accP[r][2] = ffma2(p01, bB.x, accP[r][2]);
            accP[r][3] = ffma2(p01, bB.y, accP[r][3]);
            accP[r][0] = ffma2(p23, bC.x, accP[r][0]);
            accP[r][1] = ffma2(p23, bC.y, accP[r][1]);
            accP[r][2] = ffma2(p23, bD.x, accP[r][2]);
            accP[r][3] = ffma2(p23, bD.y, accP[r][3]);
        }
    }

    float4 bv = make_float4(0.f, 0.f, 0.f, 0.f);
    if (BIAS) bv = *(const float4*)(bias + c);
    #pragma unroll
    for (int r = 0; r < 8; r++) {
        float lo, hi;
        float4 o;
        upk2(accP[r][0], lo, hi); o.x = lo + hi + bv.x;
        upk2(accP[r][1], lo, hi); o.y = lo + hi + bv.y;
        upk2(accP[r][2], lo, hi); o.z = lo + hi + bv.z;
        upk2(accP[r][3], lo, hi); o.w = lo + hi + bv.w;
        *(float4*)(out + (m0 + r) * CC + c) = o;
    }
}

// ---------------- SPMM 64-ch: warp per (b,row), 2 edges in flight -------------
// lanes 0-15 = even edges, 16-31 = odd edges; lane owns channel quad (lane&15)*4.
// Halves combined via shfl_xor(16); half 0 writes the float4 result.
__global__ void k_spmm(const float* __restrict__ xw, const float* __restrict__ bias,
                       float* __restrict__ out, int fuse_relu) {
    int gw = (blockIdx.x * blockDim.x + threadIdx.x) >> 5;
    int lane = threadIdx.x & 31;
    if (gw >= NB * NN) return;
    int b = gw / NN;
    int r = gw - b * NN;
    int half = lane >> 4;
    int c0 = (lane & 15) * 4;

    const float* base = xw + (size_t)b * NNCC;
    float4 acc = make_float4(0.f, 0.f, 0.f, 0.f);
    if (half == 0) {
        float di = g_dinv[r];
        float sl = di * di;
        float4 sv = *(const float4*)(base + (size_t)r * CC + c0);
        acc.x = sv.x * sl; acc.y = sv.y * sl; acc.z = sv.z * sl; acc.w = sv.w * sl;
    }

    int s = g_rowptr[r];
    int e = g_rowptr[r + 1];
    int i = s;
    for (; i + 4 <= e; i += 4) {               // 2 edge-pairs per iter
        int2 eA = g_csr[i + half];
        int2 eB = g_csr[i + 2 + half];
        float wA = __int_as_float(eA.y);
        float wB = __int_as_float(eB.y);
        float4 vA = *(const float4*)(base + (size_t)eA.x * CC + c0);
        float4 vB = *(const float4*)(base + (size_t)eB.x * CC + c0);
        acc.x += wA * vA.x + wB * vB.x;
        acc.y += wA * vA.y + wB * vB.y;
        acc.z += wA * vA.z + wB * vB.z;
        acc.w += wA * vA.w + wB * vB.w;
    }
    if (i + 2 <= e) {                          // one edge-pair
        int2 eA = g_csr[i + half];
        float wA = __int_as_float(eA.y);
        float4 vA = *(const float4*)(base + (size_t)eA.x * CC + c0);
        acc.x += wA * vA.x; acc.y += wA * vA.y;
        acc.z += wA * vA.z; acc.w += wA * vA.w;
        i += 2;
    }
    if (i < e && half == 0) {                  // odd remainder edge
        int2 eA = g_csr[i];
        float wA = __int_as_float(eA.y);
        float4 vA = *(const float4*)(base + (size_t)eA.x * CC + c0);
        acc.x += wA * vA.x; acc.y += wA * vA.y;
        acc.z += wA * vA.z; acc.w += wA * vA.w;
    }

    // combine even/odd halves (both end with the full sum)
    acc.x += __shfl_xor_sync(0xffffffffu, acc.x, 16);
    acc.y += __shfl_xor_sync(0xffffffffu, acc.y, 16);
    acc.z += __shfl_xor_sync(0xffffffffu, acc.z, 16);
    acc.w += __shfl_xor_sync(0xffffffffu, acc.w, 16);

    if (half == 0) {
        float4 bq = *(const float4*)(bias + c0);
        acc.x += bq.x; acc.y += bq.y; acc.z += bq.z; acc.w += bq.w;
        if (fuse_relu) {
            acc.x = fmaxf(acc.x, 0.f); acc.y = fmaxf(acc.y, 0.f);
            acc.z = fmaxf(acc.z, 0.f); acc.w = fmaxf(acc.w, 0.f);
        }
        *(float4*)(out + ((size_t)b * NN + r) * CC + c0) = acc;
    }
}

// ---------------- BatchNorm stats + last-block finalize ----------------------
__global__ void k_bn_stat(const float* __restrict__ h, int slot,
                          const float* __restrict__ gam) {
    int c = threadIdx.x & 63;
    int rs = threadIdx.x >> 6;
    size_t row0 = (size_t)blockIdx.x * 256;
    float s = 0.f, s2 = 0.f;
    for (int j = rs; j < 256; j += 4) {
        size_t row = row0 + j;
        if (row < NTOT) {
            float v = h[row * CC + c];
            s += v; s2 += v * v;
        }
    }
    __shared__ float ss[256], ss2[256];
    __shared__ int last;
    ss[threadIdx.x] = s; ss2[threadIdx.x] = s2;
    __syncthreads();
    if (rs == 0) {
        double ds  = (double)ss[c]  + (double)ss[64 + c]  + (double)ss[128 + c]  + (double)ss[192 + c];
        double ds2 = (double)ss2[c] + (double)ss2[64 + c] + (double)ss2[128 + c] + (double)ss2[192 + c];
        atomicAdd(&g_bnsum[slot * CC + c], ds);
        atomicAdd(&g_bnsumsq[slot * CC + c], ds2);
        __threadfence();
    }
    __syncthreads();
    if (threadIdx.x == 0) {
        int t = atomicAdd(&g_bnflag[slot], 1);
        last = (t == (int)gridDim.x - 1) ? 1 : 0;
    }
    __syncthreads();
    if (last && threadIdx.x < CC) {
        __threadfence();
        const double invN = 1.0 / (double)(NB * NN);
        double mu = g_bnsum[slot * CC + threadIdx.x] * invN;
        double var = g_bnsumsq[slot * CC + threadIdx.x] * invN - mu * mu;
        g_bnmu[slot * CC + threadIdx.x] = (float)mu;
        g_bnsc[slot * CC + threadIdx.x] = rsqrtf((float)var + BN_EPS) * gam[threadIdx.x];
    }
}

// ---------------- top-k sort pool + MLP1 + MLP2 (merged, 1024 thr) -----------
__device__ __forceinline__ void argmax_red32(float& v, int& i) {
    #pragma unroll
    for (int off = 16; off; off >>= 1) {
        float v2 = __shfl_down_sync(0xffffffffu, v, off);
        int   i2 = __shfl_down_sync(0xffffffffu, i, off);
        if (v2 > v || (v2 == v && i2 < i)) { v = v2; i = i2; }
    }
}

#define NSLC 32
#define SLW32 ((FLATN + NSLC - 1) / NSLC)   // 196
__global__ void k_topk_mlp(const float* __restrict__ x, const float* __restrict__ age,
                           const float* __restrict__ mW0, const float* __restrict__ mb0,
                           const float* __restrict__ mW1, const float* __restrict__ mb1,
                           const float* __restrict__ be0, const float* __restrict__ be1,
                           float* __restrict__ out) {
    __shared__ __align__(16) float flat[FLATN + 3];    // padded; phase1: key[5000]
    __shared__ __align__(16) float part[NSLC * FH];    // slice partials
    __shared__ __align__(16) float hm_s[FH];
    __shared__ float swv[32];
    __shared__ int   swi[32];
    __shared__ int   sel[KP];
    int b = blockIdx.x;
    int t = threadIdx.x;           // 0..1023
    int lane = t & 31, wid = t >> 5;

    // ---- phase 0 (block 0): restore zero invariant for next graph replay ----
    if (b == 0) {
        for (int i = t; i < NN; i += 1024) { g_deg[i] = 0.f; g_count[i] = 0; g_cursor[i] = 0; }
        if (t < 2 * CC) { g_bnsum[t] = 0.0; g_bnsumsq[t] = 0.0; }
        if (t < 2) g_bnflag[t] = 0;
    }

    // ---- phase 1: top-30 of h3[:, :, 63] (stable: val desc, idx asc) ----
    float* key = flat;
    for (int n = t; n < NN; n += 1024)
        key[n] = g_h3[((size_t)b * NN + n) * CC + 63];
    __syncthreads();
    for (int it = 0; it < KP; it++) {
        float best = -INFINITY;
        int bidx = NN;
        for (int n = t; n < NN; n += 1024) {
            float v = key[n];
            if (v > best || (v == best && n < bidx)) { best = v; bidx = n; }
        }
        argmax_red32(best, bidx);
        if (lane == 0) { swv[wid] = best; swi[wid] = bidx; }
        __syncthreads();
        if (wid == 0) {
            float v = swv[lane];
            int i = swi[lane];
            argmax_red32(v, i);
            if (lane == 0) { sel[it] = i; key[i] = -INFINITY; }
        }
        __syncthreads();
    }

    // ---- phase 2: gather flat features (BN+relu applied to h1/h2) ----
    for (int i = t; i < KP * FTOT; i += 1024) {
        int k = i / FTOT;
        int f = i - k * FTOT;
        int n = sel[k];
        size_t bn = (size_t)b * NN + n;
        float v;
        if (f < DIN) {
            v = x[bn * DIN + f];
        } else if (f < DIN + CC) {
            int c = f - DIN;
            v = fmaxf((g_h1[bn * CC + c] - g_bnmu[c]) * g_bnsc[c] + be0[c], 0.f);
        } else if (f < DIN + 2 * CC) {
            int c = f - DIN - CC;
            v = fmaxf((g_h2[bn * CC + c] - g_bnmu[CC + c]) * g_bnsc[CC + c] + be1[c], 0.f);
        } else {
            v = g_h3[bn * CC + (f - DIN - 2 * CC)];
        }
        flat[i] = v;
    }
    if (t == 0) flat[KP * FTOT] = age[b];
    __syncthreads();

    // ---- MLP layer 1: thread = (neuron-quad = lane, slice = warp) ----
    {
        int n0 = lane * 4;          // neuron quad base (lane 0..31 covers 128)
        int slice = wid;            // 0..31
        int i0 = slice * SLW32;
        int i1 = min(i0 + SLW32, FLATN);
        float4 a = make_float4(0.f, 0.f, 0.f, 0.f);
        for (int i = i0; i < i1; i++) {
            float fv = flat[i];
            float4 w = *(const float4*)(mW0 + (size_t)i * FH + n0);
            a.x += fv * w.x; a.y += fv * w.y; a.z += fv * w.z; a.w += fv * w.w;
        }
        *(float4*)(&part[slice * FH + n0]) = a;
    }
    __syncthreads();

    if (t < FH) {
        float accn = mb0[t];
        #pragma unroll 8
        for (int sl2 = 0; sl2 < NSLC; sl2++) accn += part[sl2 * FH + t];
        hm_s[t] = fmaxf(accn, 0.f);
    }
    __syncthreads();

    // ---- MLP layer 2 + log_softmax (warp 0) ----
    if (t < 32) {
        float p0 = 0.f, p1 = 0.f;
        #pragma unroll
        for (int jj = t; jj < FH; jj += 32) {
            float v = hm_s[jj];
            float2 w = *(const float2*)(mW1 + jj * 2);
            p0 += v * w.x; p1 += v * w.y;
        }
        #pragma unroll
        for (int off = 16; off; off >>= 1) {
            p0 += __shfl_down_sync(0xffffffffu, p0, off);
            p1 += __shfl_down_sync(0xffffffffu, p1, off);
        }
        if (t == 0) {
            float a0 = p0 + mb1[0], a1 = p1 + mb1[1];
            float m = fmaxf(a0, a1);
            float lse = m + logf(expf(a0 - m) + expf(a1 - m));
            out[b * 2 + 0] = a0 - lse;
            out[b * 2 + 1] = a1 - lse;
        }
    }
}

// ---------------- driver ------------------------------------------------------
extern "C" void kernel_launch(void* const* d_in, const int* in_sizes, int n_in,
                              void* d_out, int out_size) {
    const float* x    = (const float*)d_in[0];
    const float* age  = (const float*)d_in[1];
    const float* attr = (const float*)d_in[2];
    const float* W0   = (const float*)d_in[3];
    const float* b0   = (const float*)d_in[4];
    const float* W1   = (const float*)d_in[5];
    const float* b1   = (const float*)d_in[6];
    const float* W2   = (const float*)d_in[7];
    const float* b2   = (const float*)d_in[8];
    const float* g0   = (const float*)d_in[9];
    const float* be0  = (const float*)d_in[10];
    const float* g1   = (const float*)d_in[11];
    const float* be1  = (const float*)d_in[12];
    const float* mW0  = (const float*)d_in[13];
    const float* mb0  = (const float*)d_in[14];
    const float* mW1  = (const float*)d_in[15];
    const float* mb1  = (const float*)d_in[16];
    const int*   erow = (const int*)d_in[17];
    const int*   ecol = (const int*)d_in[18];
    float* out = (float*)d_out;

    // Resolve REAL device addresses of scratch symbols (host-side query; capture-safe).
    float *p_ax = nullptr, *p_xw = nullptr, *p_h1 = nullptr, *p_h2 = nullptr, *p_h3 = nullptr;
    cudaGetSymbolAddress((void**)&p_ax, g_ax);
    cudaGetSymbolAddress((void**)&p_xw, g_xw);
    cudaGetSymbolAddress((void**)&p_h1, g_h1);
    cudaGetSymbolAddress((void**)&p_h2, g_h2);
    cudaGetSymbolAddress((void**)&p_h3, g_h3);

    // graph normalization + CSR build (3 launches; zero invariant maintained
    // by k_topk_mlp block 0 at the end of the previous run / module load)
    k_deg_accum<<<(NE + 255) / 256, 256>>>(attr, erow);
    k_dinv_scan<<<1, 1024>>>();
    k_build_csr<<<(NE + 255) / 256, 256>>>(attr, erow, ecol);

    const int spmm16_blocks = (NN * (NB / 2) * 32 + 255) / 256; // 2 batches per warp
    const int spmm_blocks = (NB * NN * 32 + 255) / 256;         // warp per (b,row)
    const int gemm_blocks = (int)(NTOT / 128);                  // 1250, exact
    const int bn_stat_blocks = (int)((NTOT + 255) / 256);       // 625, exact

    // layer 0: aggregate (A X) then dense (AX)@W0 + b0; h1 stored RAW
    k_spmm16<<<spmm16_blocks, 256>>>(x, p_ax);
    k_gemm_rb<DIN, true, false><<<gemm_blocks, 256>>>(p_ax, W0, b0, nullptr, 0, p_h1);
    k_bn_stat<<<bn_stat_blocks, 256>>>(p_h1, 0, g0);

    // layer 1: xw = bnrelu0(h1) @ W1 (BN fused into input load); h2 RAW
    k_gemm_rb<CC, false, true><<<gemm_blocks, 256>>>(p_h1, W1, nullptr, be0, 0, p_xw);
    k_spmm<<<spmm_blocks, 256>>>(p_xw, b1, p_h2, 0);
    k_bn_stat<<<bn_stat_blocks, 256>>>(p_h2, 1, g1);

    // layer 2: xw = bnrelu1(h2) @ W2; h3 = relu(A xw + b2)
    k_gemm_rb<CC, false, true><<<gemm_blocks, 256>>>(p_h2, W2, nullptr, be1, 1, p_xw);
    k_spmm<<<spmm_blocks, 256>>>(p_xw, b2, p_h3, 1);

    // sort pooling + MLP head (fully fused) + scratch re-zero for next replay
    k_topk_mlp<<<NB, 1024>>>(x, age, mW0, mb0, mW1, mb1, be0, be1, out);
}